// round 2
// baseline (speedup 1.0000x reference)
#include <cuda_runtime.h>
#include <cuda_bf16.h>
#include <math.h>

// Problem constants: B=4, N=1024, D=128, H=64
#define BATCH 4
#define NSEQ  1024
#define DDIM  128
#define HDIM  64
#define BN    (BATCH * NSEQ)   // 4096

// Scratch for projections (allocation-free rule: __device__ globals)
__device__ float g_pre[BN * HDIM];   // emb @ Wa + b1   (indexed by i)
__device__ float g_hj [BN * HDIM];   // emb @ Wb        (indexed by j)

// ---------------------------------------------------------------------------
// Packed f32x2 helpers (sm_103a). ptxas coalesces the b64 movs into register
// pairs in the common case.
// ---------------------------------------------------------------------------
__device__ __forceinline__ float2 add2(float2 a, float2 b) {
    float2 r;
    asm("{\n\t.reg .b64 ra, rb, rc;\n\t"
        "mov.b64 ra, {%2,%3};\n\t"
        "mov.b64 rb, {%4,%5};\n\t"
        "add.rn.f32x2 rc, ra, rb;\n\t"
        "mov.b64 {%0,%1}, rc;\n\t}"
        : "=f"(r.x), "=f"(r.y)
        : "f"(a.x), "f"(a.y), "f"(b.x), "f"(b.y));
    return r;
}

__device__ __forceinline__ void fma2(float2& d, float2 a, float2 b) {
    asm("{\n\t.reg .b64 ra, rb, rd;\n\t"
        "mov.b64 ra, {%2,%3};\n\t"
        "mov.b64 rb, {%4,%5};\n\t"
        "mov.b64 rd, {%6,%7};\n\t"
        "fma.rn.f32x2 rd, ra, rb, rd;\n\t"
        "mov.b64 {%0,%1}, rd;\n\t}"
        : "=f"(d.x), "=f"(d.y)
        : "f"(a.x), "f"(a.y), "f"(b.x), "f"(b.y), "f"(d.x), "f"(d.y));
}

// ---------------------------------------------------------------------------
// Kernel A: projections.  One block = 32 rows of (b*N) x 128 input.
// W1 (256x64) is loaded transposed+split into smem as w1t[col][d] with
// stride 130 (2-way-conflict-free for the strided column loads).
//   col < 64  -> Wa column (pre),  col >= 64 -> Wb column (hj)
// Each thread computes a 4x4 register tile over (row, col).
// dyn smem = (128*130 + 32*128)*4 = 82944 B
// ---------------------------------------------------------------------------
__global__ __launch_bounds__(256) void precompute_kernel(
    const float* __restrict__ emb, const float* __restrict__ W1,
    const float* __restrict__ b1)
{
    extern __shared__ float shA[];
    float* w1t = shA;               // 128 * 130
    float* es  = shA + 128 * 130;   // 32 * 128
    const int t = threadIdx.x;
    const int row0 = blockIdx.x * 32;

    // Load W1 transposed/split: coalesced global reads (c fastest), strided smem writes
    for (int idx = t; idx < 128 * 128; idx += 256) {
        int d = idx >> 7, c = idx & 127;
        float v = (c < 64) ? W1[d * 64 + c] : W1[(128 + d) * 64 + (c - 64)];
        w1t[c * 130 + d] = v;
    }
    for (int idx = t; idx < 32 * 128; idx += 256)
        es[idx] = emb[row0 * 128 + idx];
    __syncthreads();

    const int colg = t & 31, rowg = t >> 5;
    const int c0 = colg * 4, r0 = rowg * 4;

    float acc[4][4];
    #pragma unroll
    for (int rr = 0; rr < 4; rr++)
        #pragma unroll
        for (int cc = 0; cc < 4; cc++)
            acc[rr][cc] = (c0 + cc < 64) ? b1[c0 + cc] : 0.0f;

    #pragma unroll 8
    for (int d = 0; d < 128; d += 2) {
        float2 e[4], w[4];
        #pragma unroll
        for (int rr = 0; rr < 4; rr++)
            e[rr] = *(const float2*)(es + (r0 + rr) * 128 + d);
        #pragma unroll
        for (int cc = 0; cc < 4; cc++)
            w[cc] = *(const float2*)(w1t + (c0 + cc) * 130 + d);
        #pragma unroll
        for (int rr = 0; rr < 4; rr++)
            #pragma unroll
            for (int cc = 0; cc < 4; cc++) {
                acc[rr][cc] = fmaf(e[rr].x, w[cc].x, acc[rr][cc]);
                acc[rr][cc] = fmaf(e[rr].y, w[cc].y, acc[rr][cc]);
            }
    }

    #pragma unroll
    for (int rr = 0; rr < 4; rr++)
        #pragma unroll
        for (int cc = 0; cc < 4; cc++) {
            int col = c0 + cc;
            int row = row0 + r0 + rr;
            if (col < 64) g_pre[row * 64 + col] = acc[rr][cc];
            else          g_hj [row * 64 + col - 64] = acc[rr][cc];
        }
}

// ---------------------------------------------------------------------------
// Kernel B: pairwise core.  Block tile: 128 (i) x 64 (j), 256 threads (16x16),
// per-thread micro-tile MI=8 x MJ=4, h processed 2-at-a-time with f32x2.
// smem: pre_s[128][64] (stride 64, broadcast loads), hj_s[64][66] (stride 66
// makes the tx-strided loads conflict-free), w2s[64].
// Writes t = tanh(s_ij + b2) into out (pre-symmetrization).
// dyn smem = (128*64 + 64*66 + 64)*4 = 49920 B
// ---------------------------------------------------------------------------
__global__ __launch_bounds__(256, 2) void pair_kernel(
    const float* __restrict__ W2, const float* __restrict__ b2,
    float* __restrict__ out)
{
    extern __shared__ float shB[];
    float* pre_s = shB;                       // 128*64
    float* hj_s  = shB + 128 * 64;            // 64*66
    float* w2s   = hj_s + 64 * 66;            // 64

    const int t  = threadIdx.x;
    const int jt = blockIdx.x;   // 0..15  (64-wide j tiles)
    const int it = blockIdx.y;   // 0..7   (128-wide i tiles)
    const int b  = blockIdx.z;

    const float* preG = g_pre + (b * NSEQ + it * 128) * 64;
    const float* hjG  = g_hj  + (b * NSEQ + jt * 64)  * 64;

    for (int idx = t; idx < 128 * 64; idx += 256)
        pre_s[idx] = preG[idx];
    for (int idx = t; idx < 64 * 64; idx += 256)
        hj_s[(idx >> 6) * 66 + (idx & 63)] = hjG[idx];
    if (t < 64) w2s[t] = W2[t];
    __syncthreads();

    const int tx = t & 15;   // j sub-index (strided by 16)
    const int ty = t >> 4;   // i sub-index (strided by 16)

    float2 acc[8][4];
    #pragma unroll
    for (int r = 0; r < 8; r++)
        #pragma unroll
        for (int c = 0; c < 4; c++)
            acc[r][c] = make_float2(0.0f, 0.0f);

    const float* pa = pre_s + ty * 64;
    const float* pb = hj_s  + tx * 66;

    #pragma unroll 4
    for (int h = 0; h < 64; h += 2) {
        float2 wv = *(const float2*)(w2s + h);
        float2 av[8], bv[4];
        #pragma unroll
        for (int r = 0; r < 8; r++)
            av[r] = *(const float2*)(pa + (16 * r) * 64 + h);
        #pragma unroll
        for (int c = 0; c < 4; c++)
            bv[c] = *(const float2*)(pb + (16 * c) * 66 + h);
        #pragma unroll
        for (int r = 0; r < 8; r++)
            #pragma unroll
            for (int c = 0; c < 4; c++) {
                float2 s = add2(av[r], bv[c]);
                s.x = fmaxf(s.x, 0.0f);          // FMNMX -> alu pipe
                s.y = fmaxf(s.y, 0.0f);
                fma2(acc[r][c], s, wv);
            }
    }

    const float b2v = b2[0];
    float* outB = out + (size_t)b * NSEQ * NSEQ;
    #pragma unroll
    for (int r = 0; r < 8; r++) {
        int i = it * 128 + ty + 16 * r;
        #pragma unroll
        for (int c = 0; c < 4; c++) {
            int j = jt * 64 + tx + 16 * c;
            float s = acc[r][c].x + acc[r][c].y + b2v;
            outB[i * NSEQ + j] = tanhf(s);
        }
    }
}

// ---------------------------------------------------------------------------
// Kernel C: in-place symmetrize + negate.
// out[i][j] = -(t[i][j] + t[j][i]) * 0.5.  Each block owns the (p,q)/(q,p)
// tile pair (p<=q), so in-place is race-free.  32x32 tiles, 32x8 threads.
// ---------------------------------------------------------------------------
__global__ void sym_kernel(float* __restrict__ out)
{
    const int p = blockIdx.x, q = blockIdx.y, b = blockIdx.z;
    if (p > q) return;
    __shared__ float sA[32][33];
    __shared__ float sB[32][33];
    float* base = out + (size_t)b * NSEQ * NSEQ;
    const int tx = threadIdx.x, ty = threadIdx.y;

    #pragma unroll
    for (int k = 0; k < 4; k++) {
        int r = ty + 8 * k;
        sA[r][tx] = base[(p * 32 + r) * NSEQ + q * 32 + tx];
        sB[r][tx] = base[(q * 32 + r) * NSEQ + p * 32 + tx];
    }
    __syncthreads();
    #pragma unroll
    for (int k = 0; k < 4; k++) {
        int r = ty + 8 * k;
        float v1 = -0.5f * (sA[r][tx] + sB[tx][r]);
        float v2 = -0.5f * (sB[r][tx] + sA[tx][r]);
        base[(p * 32 + r) * NSEQ + q * 32 + tx] = v1;
        base[(q * 32 + r) * NSEQ + p * 32 + tx] = v2;
    }
}

// ---------------------------------------------------------------------------
extern "C" void kernel_launch(void* const* d_in, const int* in_sizes, int n_in,
                              void* d_out, int out_size)
{
    const float* emb = (const float*)d_in[0];
    const float* W1  = (const float*)d_in[1];
    const float* b1  = (const float*)d_in[2];
    const float* W2  = (const float*)d_in[3];
    const float* b2  = (const float*)d_in[4];
    float* out = (float*)d_out;

    const int smemA = (128 * 130 + 32 * 128) * 4;        // 82944
    const int smemB = (128 * 64 + 64 * 66 + 64) * 4;     // 49920

    cudaFuncSetAttribute(precompute_kernel,
                         cudaFuncAttributeMaxDynamicSharedMemorySize, smemA);
    cudaFuncSetAttribute(pair_kernel,
                         cudaFuncAttributeMaxDynamicSharedMemorySize, smemB);

    precompute_kernel<<<BN / 32, 256, smemA>>>(emb, W1, b1);
    pair_kernel<<<dim3(16, 8, 4), 256, smemB>>>(W2, b2, out);
    sym_kernel<<<dim3(32, 32, 4), dim3(32, 8)>>>(out);
}

// round 5
// speedup vs baseline: 1.2934x; 1.2934x over previous
#include <cuda_runtime.h>
#include <cuda_bf16.h>
#include <math.h>

// Problem constants: B=4, N=1024, D=128, H=64
#define BATCH 4
#define NSEQ  1024
#define DDIM  128
#define HDIM  64
#define BN    (BATCH * NSEQ)   // 4096

// Projections stored TRANSPOSED [h][b*N+row] so precompute stores and
// pair-kernel fills are both coalesced.
__device__ float g_preT[HDIM * BN];   // emb @ Wa + b1
__device__ float g_hjT [HDIM * BN];   // emb @ Wb

// ---------------------------------------------------------------------------
// Packed f32x2 helpers (sm_103a)
// ---------------------------------------------------------------------------
__device__ __forceinline__ float2 add2(float2 a, float2 b) {
    float2 r;
    asm("{\n\t.reg .b64 ra, rb, rc;\n\t"
        "mov.b64 ra, {%2,%3};\n\t"
        "mov.b64 rb, {%4,%5};\n\t"
        "add.rn.f32x2 rc, ra, rb;\n\t"
        "mov.b64 {%0,%1}, rc;\n\t}"
        : "=f"(r.x), "=f"(r.y)
        : "f"(a.x), "f"(a.y), "f"(b.x), "f"(b.y));
    return r;
}

__device__ __forceinline__ void fma2(float2& d, float2 a, float2 b) {
    asm("{\n\t.reg .b64 ra, rb, rd;\n\t"
        "mov.b64 ra, {%2,%3};\n\t"
        "mov.b64 rb, {%4,%5};\n\t"
        "mov.b64 rd, {%6,%7};\n\t"
        "fma.rn.f32x2 rd, ra, rb, rd;\n\t"
        "mov.b64 {%0,%1}, rd;\n\t}"
        : "=f"(d.x), "=f"(d.y)
        : "f"(a.x), "f"(a.y), "f"(b.x), "f"(b.y), "f"(d.x), "f"(d.y));
}

__device__ __forceinline__ float fast_tanh(float x) {
    // tanh(x) = 1 - 2/(e^{2x}+1); exact limits at +-inf, ~1e-6 rel err.
    float e = __expf(2.0f * x);
    return 1.0f - __fdividef(2.0f, e + 1.0f);
}

// ---------------------------------------------------------------------------
// Kernel A: projections.
// Grid (64, 2): x = 64-row tile, y = half (0 -> Wa/pre (+b1), 1 -> Wb/hj).
// Block 256 thr = 8 warps. Warp w owns 8 output cols (w-loads are
// warp-broadcast -> conflict-free). Lane owns rows {lane, lane+32}
// (e-loads stride 130 words == 2 mod 32 -> conflict-free .64).
// Output stored transposed, coalesced along rows.
// dyn smem = 2 * 64*130 * 4 = 66560 B
// ---------------------------------------------------------------------------
__global__ __launch_bounds__(256) void precompute_kernel(
    const float* __restrict__ emb, const float* __restrict__ W1,
    const float* __restrict__ b1)
{
    extern __shared__ float sh[];
    float* w1t = sh;              // 64 cols * 130
    float* es  = sh + 64 * 130;   // 64 rows * 130
    const int t = threadIdx.x;
    const int row0 = blockIdx.x * 64;
    const int half = blockIdx.y;  // 0 = Wa, 1 = Wb

    // W1 slice for this half: cols c64 = 0..63, W1[(half*128 + d)*64 + c64]
    for (int idx = t; idx < 64 * 128; idx += 256) {
        int c = idx & 63, d = idx >> 6;
        w1t[c * 130 + d] = W1[(half * 128 + d) * 64 + c];
    }
    for (int idx = t; idx < 64 * 128; idx += 256) {
        int d = idx & 127, r = idx >> 7;
        es[r * 130 + d] = emb[(row0 + r) * 128 + d];
    }
    __syncthreads();

    const int lane = t & 31;
    const int w    = t >> 5;          // 0..7
    const int c0   = w * 8;           // 8 cols per warp

    float2 acc[2][8];
    #pragma unroll
    for (int rr = 0; rr < 2; rr++)
        #pragma unroll
        for (int cc = 0; cc < 8; cc++)
            acc[rr][cc] = make_float2(0.0f, 0.0f);

    const float* e0p = es + lane * 130;
    const float* e1p = es + (lane + 32) * 130;

    #pragma unroll 4
    for (int d = 0; d < 128; d += 2) {
        float2 e0 = *(const float2*)(e0p + d);
        float2 e1 = *(const float2*)(e1p + d);
        #pragma unroll
        for (int cc = 0; cc < 8; cc++) {
            float2 wv = *(const float2*)(w1t + (c0 + cc) * 130 + d);  // broadcast
            fma2(acc[0][cc], e0, wv);
            fma2(acc[1][cc], e1, wv);
        }
    }

    float* dst = half ? g_hjT : g_preT;
    #pragma unroll
    for (int rr = 0; rr < 2; rr++) {
        int rowg = row0 + lane + 32 * rr;
        #pragma unroll
        for (int cc = 0; cc < 8; cc++) {
            int col = c0 + cc;
            float s = acc[rr][cc].x + acc[rr][cc].y;
            if (half == 0) s += b1[col];
            dst[col * BN + rowg] = s;    // coalesced along rows
        }
    }
}

// ---------------------------------------------------------------------------
// Kernel B: fused pairwise core + tanh + symmetrize + negate.
// Grid (136, 4): x = unordered tile pair (I <= J) of 64-row tiles, y = batch.
// 256 threads (16x16), micro-tile 4x4 pairs, TWO accumulators per pair:
//   acc1 -> s_{I+i, J+j}   (preI_i + hjJ_j)
//   acc2 -> s_{J+j, I+i}   (preJ_j + hjI_i)
// Output v = -(tanh(s1+b2)+tanh(s2+b2))/2 written to both (i,j) and (j,i),
// the mirror through a padded smem transpose for coalescing.
// smem: 4 tiles of 64x66 + w2[64] = 67840 B
// ---------------------------------------------------------------------------
__global__ __launch_bounds__(256, 2) void pair_sym_kernel(
    const float* __restrict__ W2, const float* __restrict__ b2,
    float* __restrict__ out)
{
    extern __shared__ float shB[];
    float* preI = shB;                 // 64*66
    float* hjI  = shB + 1 * 64 * 66;
    float* preJ = shB + 2 * 64 * 66;
    float* hjJ  = shB + 3 * 64 * 66;
    float* w2s  = shB + 4 * 64 * 66;   // 64

    const int t = threadIdx.x;
    const int b = blockIdx.y;

    // Decode unordered pair (I, J), I <= J, from blockIdx.x (uniform loop)
    int p = blockIdx.x;
    int I = 0;
    while (p >= 16 - I) { p -= 16 - I; I++; }
    const int J = I + p;

    const int baseI = b * NSEQ + I * 64;
    const int baseJ = b * NSEQ + J * 64;

    // Fill smem tiles from transposed globals: coalesced 256B runs per h.
    for (int idx = t; idx < 64 * 64; idx += 256) {
        int h = idx >> 6, rr = idx & 63;
        float vpI = g_preT[h * BN + baseI + rr];
        float vhI = g_hjT [h * BN + baseI + rr];
        float vpJ = g_preT[h * BN + baseJ + rr];
        float vhJ = g_hjT [h * BN + baseJ + rr];
        preI[rr * 66 + h] = vpI;
        hjI [rr * 66 + h] = vhI;
        preJ[rr * 66 + h] = vpJ;
        hjJ [rr * 66 + h] = vhJ;
    }
    if (t < 64) w2s[t] = W2[t];
    __syncthreads();

    const int tx = t & 15;   // j sub-index
    const int ty = t >> 4;   // i sub-index

    float2 acc1[4][4], acc2[4][4];
    #pragma unroll
    for (int r = 0; r < 4; r++)
        #pragma unroll
        for (int c = 0; c < 4; c++) {
            acc1[r][c] = make_float2(0.0f, 0.0f);
            acc2[r][c] = make_float2(0.0f, 0.0f);
        }

    const float* pAI = preI + ty * 66;   // rows ty + 16r  (broadcast across warp)
    const float* pHI = hjI  + ty * 66;
    const float* pPJ = preJ + tx * 66;   // rows tx + 16c  (stride 66 -> conflict-free)
    const float* pHJ = hjJ  + tx * 66;

    #pragma unroll 2
    for (int h = 0; h < 64; h += 2) {
        float2 wv = *(const float2*)(w2s + h);
        float2 aI[4], bJ[4], pJ[4], bI[4];
        #pragma unroll
        for (int r = 0; r < 4; r++) {
            aI[r] = *(const float2*)(pAI + (16 * r) * 66 + h);
            bI[r] = *(const float2*)(pHI + (16 * r) * 66 + h);
        }
        #pragma unroll
        for (int c = 0; c < 4; c++) {
            bJ[c] = *(const float2*)(pHJ + (16 * c) * 66 + h);
            pJ[c] = *(const float2*)(pPJ + (16 * c) * 66 + h);
        }
        #pragma unroll
        for (int r = 0; r < 4; r++)
            #pragma unroll
            for (int c = 0; c < 4; c++) {
                float2 s1 = add2(aI[r], bJ[c]);
                s1.x = fmaxf(s1.x, 0.0f);
                s1.y = fmaxf(s1.y, 0.0f);
                fma2(acc1[r][c], s1, wv);
                float2 s2 = add2(pJ[c], bI[r]);
                s2.x = fmaxf(s2.x, 0.0f);
                s2.y = fmaxf(s2.y, 0.0f);
                fma2(acc2[r][c], s2, wv);
            }
    }

    const float b2v = b2[0];
    float* outB = out + (size_t)b * NSEQ * NSEQ;

    // Final values + direct (coalesced) store of out[I+i][J+j]
    float v[4][4];
    #pragma unroll
    for (int r = 0; r < 4; r++) {
        int i = ty + 16 * r;
        #pragma unroll
        for (int c = 0; c < 4; c++) {
            int j = tx + 16 * c;
            float s1 = acc1[r][c].x + acc1[r][c].y + b2v;
            float s2 = acc2[r][c].x + acc2[r][c].y + b2v;
            float vv = -0.5f * (fast_tanh(s1) + fast_tanh(s2));
            v[r][c] = vv;
            outB[(I * 64 + i) * NSEQ + (J * 64 + j)] = vv;
        }
    }

    // Mirror store out[J+j][I+i] via padded smem transpose (stride 65).
    __syncthreads();                 // done reading preI region
    float* vs = shB;                 // reuse: 64 * 65
    #pragma unroll
    for (int r = 0; r < 4; r++)
        #pragma unroll
        for (int c = 0; c < 4; c++)
            vs[(ty + 16 * r) * 65 + (tx + 16 * c)] = v[r][c];
    __syncthreads();
    #pragma unroll
    for (int r = 0; r < 4; r++) {
        int jj = ty + 16 * r;
        #pragma unroll
        for (int c = 0; c < 4; c++) {
            int ii = tx + 16 * c;
            outB[(J * 64 + jj) * NSEQ + (I * 64 + ii)] = vs[ii * 65 + jj];
        }
    }
}

// ---------------------------------------------------------------------------
extern "C" void kernel_launch(void* const* d_in, const int* in_sizes, int n_in,
                              void* d_out, int out_size)
{
    const float* emb = (const float*)d_in[0];
    const float* W1  = (const float*)d_in[1];
    const float* b1  = (const float*)d_in[2];
    const float* W2  = (const float*)d_in[3];
    const float* b2  = (const float*)d_in[4];
    float* out = (float*)d_out;

    const int smemA = 2 * 64 * 130 * 4;            // 66560
    const int smemB = (4 * 64 * 66 + 64) * 4;      // 67840

    cudaFuncSetAttribute(precompute_kernel,
                         cudaFuncAttributeMaxDynamicSharedMemorySize, smemA);
    cudaFuncSetAttribute(pair_sym_kernel,
                         cudaFuncAttributeMaxDynamicSharedMemorySize, smemB);

    precompute_kernel<<<dim3(64, 2), 256, smemA>>>(emb, W1, b1);
    pair_sym_kernel<<<dim3(136, BATCH), 256, smemB>>>(W2, b2, out);
}

// round 7
// speedup vs baseline: 1.3373x; 1.0340x over previous
#include <cuda_runtime.h>
#include <cuda_bf16.h>
#include <cstdint>
#include <math.h>

// Problem constants: B=4, N=1024, D=128, H=64
#define BATCH 4
#define NSEQ  1024
#define DDIM  128
#define HDIM  64
#define BN    (BATCH * NSEQ)   // 4096
#define CH    16               // h-chunk for the cp.async pipeline

// Projections stored [row][h] (row-major) so cp.async 8B chunks can fill the
// pair kernel's smem tiles directly (no transpose in flight).
__device__ float g_pre[BN * HDIM];   // emb @ Wa + b1
__device__ float g_hj [BN * HDIM];   // emb @ Wb

// ---------------------------------------------------------------------------
// Packed f32x2 helpers (sm_103a)
// ---------------------------------------------------------------------------
__device__ __forceinline__ float2 add2(float2 a, float2 b) {
    float2 r;
    asm("{\n\t.reg .b64 ra, rb, rc;\n\t"
        "mov.b64 ra, {%2,%3};\n\t"
        "mov.b64 rb, {%4,%5};\n\t"
        "add.rn.f32x2 rc, ra, rb;\n\t"
        "mov.b64 {%0,%1}, rc;\n\t}"
        : "=f"(r.x), "=f"(r.y)
        : "f"(a.x), "f"(a.y), "f"(b.x), "f"(b.y));
    return r;
}

__device__ __forceinline__ void fma2(float2& d, float2 a, float2 b) {
    asm("{\n\t.reg .b64 ra, rb, rd;\n\t"
        "mov.b64 ra, {%2,%3};\n\t"
        "mov.b64 rb, {%4,%5};\n\t"
        "mov.b64 rd, {%6,%7};\n\t"
        "fma.rn.f32x2 rd, ra, rb, rd;\n\t"
        "mov.b64 {%0,%1}, rd;\n\t}"
        : "=f"(d.x), "=f"(d.y)
        : "f"(a.x), "f"(a.y), "f"(b.x), "f"(b.y), "f"(d.x), "f"(d.y));
}

__device__ __forceinline__ float fast_tanh(float x) {
    float e = __expf(2.0f * x);
    return 1.0f - __fdividef(2.0f, e + 1.0f);
}

__device__ __forceinline__ void cp8(unsigned int dst, const float* src) {
    asm volatile("cp.async.ca.shared.global [%0], [%1], 8;"
                 :: "r"(dst), "l"(src));
}

// ---------------------------------------------------------------------------
// Kernel A: projections.
// Grid (64, 2): x = 64-row tile, y = half (0 -> Wa/pre (+b1), 1 -> Wb/hj).
// Warp owns 8 output cols (w-loads warp-broadcast), lane owns rows
// {lane, lane+32} (e-loads stride 130 -> conflict-free). Stores row-major
// [row][64] via two float4 per (row, colgroup).
// dyn smem = 2 * 64*130 * 4 = 66560 B
// ---------------------------------------------------------------------------
__global__ __launch_bounds__(256) void precompute_kernel(
    const float* __restrict__ emb, const float* __restrict__ W1,
    const float* __restrict__ b1)
{
    extern __shared__ float sh[];
    float* w1t = sh;              // 64 cols * 130
    float* es  = sh + 64 * 130;   // 64 rows * 130
    const int t = threadIdx.x;
    const int row0 = blockIdx.x * 64;
    const int half = blockIdx.y;  // 0 = Wa, 1 = Wb

    for (int idx = t; idx < 64 * 128; idx += 256) {
        int c = idx & 63, d = idx >> 6;
        w1t[c * 130 + d] = W1[(half * 128 + d) * 64 + c];
    }
    for (int idx = t; idx < 64 * 128; idx += 256) {
        int d = idx & 127, r = idx >> 7;
        es[r * 130 + d] = emb[(row0 + r) * 128 + d];
    }
    __syncthreads();

    const int lane = t & 31;
    const int w    = t >> 5;
    const int c0   = w * 8;

    float2 acc[2][8];
    #pragma unroll
    for (int rr = 0; rr < 2; rr++)
        #pragma unroll
        for (int cc = 0; cc < 8; cc++)
            acc[rr][cc] = make_float2(0.0f, 0.0f);

    const float* e0p = es + lane * 130;
    const float* e1p = es + (lane + 32) * 130;

    #pragma unroll 4
    for (int d = 0; d < 128; d += 2) {
        float2 e0 = *(const float2*)(e0p + d);
        float2 e1 = *(const float2*)(e1p + d);
        #pragma unroll
        for (int cc = 0; cc < 8; cc++) {
            float2 wv = *(const float2*)(w1t + (c0 + cc) * 130 + d);
            fma2(acc[0][cc], e0, wv);
            fma2(acc[1][cc], e1, wv);
        }
    }

    float* dst = half ? g_hj : g_pre;
    #pragma unroll
    for (int rr = 0; rr < 2; rr++) {
        int rowg = row0 + lane + 32 * rr;
        float s[8];
        #pragma unroll
        for (int cc = 0; cc < 8; cc++) {
            s[cc] = acc[rr][cc].x + acc[rr][cc].y;
            if (half == 0) s[cc] += b1[c0 + cc];
        }
        *(float4*)(dst + rowg * 64 + c0)     = make_float4(s[0], s[1], s[2], s[3]);
        *(float4*)(dst + rowg * 64 + c0 + 4) = make_float4(s[4], s[5], s[6], s[7]);
    }
}

// ---------------------------------------------------------------------------
// Kernel B: fused pairwise core + tanh + symmetrize + negate, with a
// cp.async double-buffered pipeline over 16-h chunks.
//
// Grid (136, 4): x = unordered tile pair (I <= J), y = batch.
// smem stage (2x): 4 tiles [64 rows][CH + 2 pad] -> fill 8B cp.async chunks,
// compute reads float2 (stride 18 words -> conflict-free for the tx-strided
// loads; gcd(18,32)=2 covers all 32 banks with .64).
// dyn smem = (2*4*64*18 + 64) * 4 = 37120 B
// ---------------------------------------------------------------------------
#define TSTRIDE (CH + 2)             // 18 words per row
#define ARRW    (64 * TSTRIDE)       // 1152 words per tile
#define STAGEW  (4 * ARRW)           // 4608 words per stage

__global__ __launch_bounds__(256, 2) void pair_sym_kernel(
    const float* __restrict__ W2, const float* __restrict__ b2,
    float* __restrict__ out)
{
    extern __shared__ float shB[];
    float* w2s = shB + 2 * STAGEW;   // 64

    const int t = threadIdx.x;
    const int b = blockIdx.y;

    // Decode unordered pair (I, J), I <= J
    int p = blockIdx.x;
    int I = 0;
    while (p >= 16 - I) { p -= 16 - I; I++; }
    const int J = I + p;

    const int baseI = b * NSEQ + I * 64;
    const int baseJ = b * NSEQ + J * 64;

    // Per-thread fill assignment: arr fixed per 64-thread group.
    const int arr = t >> 6;          // 0..3
    const int sub = t & 63;
    const float* srcbase =
        (arr == 0) ? g_pre + baseI * 64 :
        (arr == 1) ? g_hj  + baseI * 64 :
        (arr == 2) ? g_pre + baseJ * 64 :
                     g_hj  + baseJ * 64;
    const unsigned int sbase = (unsigned int)__cvta_generic_to_shared(shB);
    const unsigned int dbase = sbase + (unsigned int)(arr * ARRW) * 4u;

    if (t < 64) w2s[t] = W2[t];

    // issue one 16-h chunk into a stage: 8 cp.async of 8B per thread
    auto issue_chunk = [&](int chunk, int stage) {
        const float* s = srcbase + chunk * CH;
        const unsigned int d0 = dbase + (unsigned int)(stage * STAGEW) * 4u;
        #pragma unroll
        for (int e = 0; e < 8; e++) {
            int idx = sub + 64 * e;          // 0..511
            int row = idx >> 3;
            int hh  = (idx & 7) * 2;
            cp8(d0 + (unsigned int)(row * TSTRIDE + hh) * 4u, s + row * 64 + hh);
        }
        asm volatile("cp.async.commit_group;");
    };

    issue_chunk(0, 0);
    issue_chunk(1, 1);

    const int tx = t & 15;
    const int ty = t >> 4;

    float2 acc1[4][4], acc2[4][4];
    #pragma unroll
    for (int r = 0; r < 4; r++)
        #pragma unroll
        for (int c = 0; c < 4; c++) {
            acc1[r][c] = make_float2(0.0f, 0.0f);
            acc2[r][c] = make_float2(0.0f, 0.0f);
        }

    #pragma unroll
    for (int cnk = 0; cnk < 4; cnk++) {
        if (cnk < 3) asm volatile("cp.async.wait_group 1;");
        else         asm volatile("cp.async.wait_group 0;");
        __syncthreads();

        const float* st   = shB + (cnk & 1) * STAGEW;
        const float* preI = st;
        const float* hjI  = st + ARRW;
        const float* preJ = st + 2 * ARRW;
        const float* hjJ  = st + 3 * ARRW;
        const float* pAI = preI + ty * TSTRIDE;
        const float* pHI = hjI  + ty * TSTRIDE;
        const float* pPJ = preJ + tx * TSTRIDE;
        const float* pHJ = hjJ  + tx * TSTRIDE;
        const float* wp  = w2s + cnk * CH;

        #pragma unroll 2
        for (int hh = 0; hh < CH; hh += 2) {
            float2 wv = *(const float2*)(wp + hh);
            float2 aI[4], bI[4], pJ[4], bJ[4];
            #pragma unroll
            for (int r = 0; r < 4; r++) {
                aI[r] = *(const float2*)(pAI + (16 * r) * TSTRIDE + hh);
                bI[r] = *(const float2*)(pHI + (16 * r) * TSTRIDE + hh);
            }
            #pragma unroll
            for (int c = 0; c < 4; c++) {
                pJ[c] = *(const float2*)(pPJ + (16 * c) * TSTRIDE + hh);
                bJ[c] = *(const float2*)(pHJ + (16 * c) * TSTRIDE + hh);
            }
            #pragma unroll
            for (int r = 0; r < 4; r++)
                #pragma unroll
                for (int c = 0; c < 4; c++) {
                    float2 s1 = add2(aI[r], bJ[c]);
                    s1.x = fmaxf(s1.x, 0.0f);
                    s1.y = fmaxf(s1.y, 0.0f);
                    fma2(acc1[r][c], s1, wv);
                    float2 s2 = add2(pJ[c], bI[r]);
                    s2.x = fmaxf(s2.x, 0.0f);
                    s2.y = fmaxf(s2.y, 0.0f);
                    fma2(acc2[r][c], s2, wv);
                }
        }

        if (cnk < 2) {
            __syncthreads();               // all warps done reading this stage
            issue_chunk(cnk + 2, cnk & 1); // refill it
        }
    }

    const float b2v = b2[0];
    float* outB = out + (size_t)b * NSEQ * NSEQ;

    // Final values + direct (coalesced) store of out[I+i][J+j]
    float v[4][4];
    #pragma unroll
    for (int r = 0; r < 4; r++) {
        int i = ty + 16 * r;
        #pragma unroll
        for (int c = 0; c < 4; c++) {
            int j = tx + 16 * c;
            float s1 = acc1[r][c].x + acc1[r][c].y + b2v;
            float s2 = acc2[r][c].x + acc2[r][c].y + b2v;
            float vv = -0.5f * (fast_tanh(s1) + fast_tanh(s2));
            v[r][c] = vv;
            outB[(I * 64 + i) * NSEQ + (J * 64 + j)] = vv;
        }
    }

    // Mirror store out[J+j][I+i] via padded smem transpose (stride 65).
    __syncthreads();
    float* vs = shB;                 // reuse: 64 * 65 = 4160 words < STAGEW
    #pragma unroll
    for (int r = 0; r < 4; r++)
        #pragma unroll
        for (int c = 0; c < 4; c++)
            vs[(ty + 16 * r) * 65 + (tx + 16 * c)] = v[r][c];
    __syncthreads();
    #pragma unroll
    for (int r = 0; r < 4; r++) {
        int jj = ty + 16 * r;
        #pragma unroll
        for (int c = 0; c < 4; c++) {
            int ii = tx + 16 * c;
            outB[(J * 64 + jj) * NSEQ + (I * 64 + ii)] = vs[ii * 65 + jj];
        }
    }
}

// ---------------------------------------------------------------------------
extern "C" void kernel_launch(void* const* d_in, const int* in_sizes, int n_in,
                              void* d_out, int out_size)
{
    const float* emb = (const float*)d_in[0];
    const float* W1  = (const float*)d_in[1];
    const float* b1  = (const float*)d_in[2];
    const float* W2  = (const float*)d_in[3];
    const float* b2  = (const float*)d_in[4];
    float* out = (float*)d_out;

    const int smemA = 2 * 64 * 130 * 4;              // 66560
    const int smemB = (2 * STAGEW + 64) * 4;         // 37120

    cudaFuncSetAttribute(precompute_kernel,
                         cudaFuncAttributeMaxDynamicSharedMemorySize, smemA);
    cudaFuncSetAttribute(pair_sym_kernel,
                         cudaFuncAttributeMaxDynamicSharedMemorySize, smemB);

    precompute_kernel<<<dim3(64, 2), 256, smemA>>>(emb, W1, b1);
    pair_sym_kernel<<<dim3(136, BATCH), 256, smemB>>>(W2, b2, out);
}

// round 8
// speedup vs baseline: 1.4018x; 1.0482x over previous
#include <cuda_runtime.h>
#include <cuda_bf16.h>
#include <cstdint>
#include <math.h>

// Problem constants: B=4, N=1024, D=128, H=64
#define BATCH 4
#define NSEQ  1024
#define DDIM  128
#define HDIM  64
#define BN    (BATCH * NSEQ)   // 4096
#define CH    16               // h-chunk for the cp.async pipeline
#define NSTAGE 3

typedef unsigned long long ull;

// Projections stored [row][h] row-major: cp.async 16B chunks fill smem directly.
__device__ float g_pre[BN * HDIM];   // emb @ Wa + b1
__device__ float g_hj [BN * HDIM];   // emb @ Wb

// ---------------------------------------------------------------------------
// Packed f32x2 helpers — pure b64 ("l") flow, no pack/unpack movs.
// ---------------------------------------------------------------------------
__device__ __forceinline__ ull add2u(ull a, ull b) {
    ull r;
    asm("add.rn.f32x2 %0, %1, %2;" : "=l"(r) : "l"(a), "l"(b));
    return r;
}
__device__ __forceinline__ void fma2u(ull& d, ull a, ull b) {
    asm("fma.rn.f32x2 %0, %1, %2, %0;" : "+l"(d) : "l"(a), "l"(b));
}
__device__ __forceinline__ ull relu2u(ull a) {
    ull r;
    asm("{\n\t.reg .f32 lo, hi;\n\t"
        "mov.b64 {lo, hi}, %1;\n\t"
        "max.f32 lo, lo, 0f00000000;\n\t"
        "max.f32 hi, hi, 0f00000000;\n\t"
        "mov.b64 %0, {lo, hi};\n\t}"
        : "=l"(r) : "l"(a));
    return r;
}
__device__ __forceinline__ float lo32(ull a) {
    return __uint_as_float((unsigned int)(a & 0xffffffffull));
}
__device__ __forceinline__ float hi32(ull a) {
    return __uint_as_float((unsigned int)(a >> 32));
}

__device__ __forceinline__ float fast_tanh(float x) {
    float e = __expf(2.0f * x);
    return 1.0f - __fdividef(2.0f, e + 1.0f);
}

__device__ __forceinline__ void cp16(unsigned int dst, const float* src) {
    asm volatile("cp.async.ca.shared.global [%0], [%1], 16;"
                 :: "r"(dst), "l"(src));
}

// ---------------------------------------------------------------------------
// Kernel A: projections (ull packed flow).
// Grid (64, 2): x = 64-row tile, y = half (0 -> Wa/pre (+b1), 1 -> Wb/hj).
// dyn smem = 2 * 64*130 * 4 = 66560 B
// ---------------------------------------------------------------------------
__global__ __launch_bounds__(256) void precompute_kernel(
    const float* __restrict__ emb, const float* __restrict__ W1,
    const float* __restrict__ b1)
{
    extern __shared__ float sh[];
    float* w1t = sh;              // 64 cols * 130
    float* es  = sh + 64 * 130;   // 64 rows * 130
    const int t = threadIdx.x;
    const int row0 = blockIdx.x * 64;
    const int half = blockIdx.y;  // 0 = Wa, 1 = Wb

    for (int idx = t; idx < 64 * 128; idx += 256) {
        int c = idx & 63, d = idx >> 6;
        w1t[c * 130 + d] = W1[(half * 128 + d) * 64 + c];
    }
    for (int idx = t; idx < 64 * 128; idx += 256) {
        int d = idx & 127, r = idx >> 7;
        es[r * 130 + d] = emb[(row0 + r) * 128 + d];
    }
    __syncthreads();

    const int lane = t & 31;
    const int w    = t >> 5;
    const int c0   = w * 8;

    ull acc[2][8];
    #pragma unroll
    for (int rr = 0; rr < 2; rr++)
        #pragma unroll
        for (int cc = 0; cc < 8; cc++)
            acc[rr][cc] = 0ull;

    const float* e0p = es + lane * 130;
    const float* e1p = es + (lane + 32) * 130;

    #pragma unroll 4
    for (int d = 0; d < 128; d += 2) {
        ull e0 = *(const ull*)(e0p + d);
        ull e1 = *(const ull*)(e1p + d);
        #pragma unroll
        for (int cc = 0; cc < 8; cc++) {
            ull wv = *(const ull*)(w1t + (c0 + cc) * 130 + d);
            fma2u(acc[0][cc], e0, wv);
            fma2u(acc[1][cc], e1, wv);
        }
    }

    float* dst = half ? g_hj : g_pre;
    #pragma unroll
    for (int rr = 0; rr < 2; rr++) {
        int rowg = row0 + lane + 32 * rr;
        float s[8];
        #pragma unroll
        for (int cc = 0; cc < 8; cc++) {
            s[cc] = lo32(acc[rr][cc]) + hi32(acc[rr][cc]);
            if (half == 0) s[cc] += b1[c0 + cc];
        }
        *(float4*)(dst + rowg * 64 + c0)     = make_float4(s[0], s[1], s[2], s[3]);
        *(float4*)(dst + rowg * 64 + c0 + 4) = make_float4(s[4], s[5], s[6], s[7]);
    }
}

// ---------------------------------------------------------------------------
// Kernel B: fused pairwise core + tanh + symmetrize + negate.
// 3-stage cp.async ring over 16-h chunks, one barrier per chunk.
// Tile row stride 20 words (16 h + 4 pad): float4 (4h) LDS with <=2-way
// bank overlap (2 crossbar phases, crossbar non-binding).
// dyn smem = (3*4*64*20 + 64) * 4 = 61696 B
// ---------------------------------------------------------------------------
#define TSTRIDE 20
#define ARRW    (64 * TSTRIDE)       // 1280 words per tile
#define STAGEW  (4 * ARRW)           // 5120 words per stage

__global__ __launch_bounds__(256, 2) void pair_sym_kernel(
    const float* __restrict__ W2, const float* __restrict__ b2,
    float* __restrict__ out)
{
    extern __shared__ float shB[];
    float* w2s = shB + NSTAGE * STAGEW;   // 64

    const int t = threadIdx.x;
    const int b = blockIdx.y;

    // Decode unordered pair (I, J), I <= J
    int p = blockIdx.x;
    int I = 0;
    while (p >= 16 - I) { p -= 16 - I; I++; }
    const int J = I + p;

    const int baseI = b * NSEQ + I * 64;
    const int baseJ = b * NSEQ + J * 64;

    // Fill assignment: 64-thread group per tile array.
    const int arr = t >> 6;          // 0..3
    const int sub = t & 63;
    const float* srcbase =
        (arr == 0) ? g_pre + baseI * 64 :
        (arr == 1) ? g_hj  + baseI * 64 :
        (arr == 2) ? g_pre + baseJ * 64 :
                     g_hj  + baseJ * 64;
    const unsigned int sbase = (unsigned int)__cvta_generic_to_shared(shB);
    const unsigned int dbase = sbase + (unsigned int)(arr * ARRW) * 4u;

    if (t < 64) w2s[t] = W2[t];

    // issue one 16-h chunk into a stage: 4 cp.async of 16B per thread
    auto issue_chunk = [&](int chunk, int stage) {
        const float* s = srcbase + chunk * CH;
        const unsigned int d0 = dbase + (unsigned int)(stage * STAGEW) * 4u;
        #pragma unroll
        for (int e = 0; e < 4; e++) {
            int idx = sub + 64 * e;          // 0..255
            int row = idx >> 2;
            int q   = (idx & 3) * 4;         // 16B quarter (4 h)
            cp16(d0 + (unsigned int)(row * TSTRIDE + q) * 4u, s + row * 64 + q);
        }
        asm volatile("cp.async.commit_group;");
    };

    issue_chunk(0, 0);
    issue_chunk(1, 1);
    issue_chunk(2, 2);

    const int tx = t & 15;
    const int ty = t >> 4;

    ull acc1[4][4], acc2[4][4];
    #pragma unroll
    for (int r = 0; r < 4; r++)
        #pragma unroll
        for (int c = 0; c < 4; c++) { acc1[r][c] = 0ull; acc2[r][c] = 0ull; }

    auto compute_chunk = [&](const float* st, const float* wp) {
        const float* pAI = st            + ty * TSTRIDE;
        const float* pHI = st + ARRW     + ty * TSTRIDE;
        const float* pPJ = st + 2 * ARRW + tx * TSTRIDE;
        const float* pHJ = st + 3 * ARRW + tx * TSTRIDE;
        #pragma unroll
        for (int hh = 0; hh < CH; hh += 4) {
            ulonglong2 wv = *(const ulonglong2*)(wp + hh);
            ulonglong2 aI[4], bI[4];
            #pragma unroll
            for (int r = 0; r < 4; r++) {
                aI[r] = *(const ulonglong2*)(pAI + (16 * r) * TSTRIDE + hh);
                bI[r] = *(const ulonglong2*)(pHI + (16 * r) * TSTRIDE + hh);
            }
            #pragma unroll
            for (int c = 0; c < 4; c++) {
                ulonglong2 pJ = *(const ulonglong2*)(pPJ + (16 * c) * TSTRIDE + hh);
                ulonglong2 bJ = *(const ulonglong2*)(pHJ + (16 * c) * TSTRIDE + hh);
                #pragma unroll
                for (int r = 0; r < 4; r++) {
                    ull s1a = relu2u(add2u(aI[r].x, bJ.x));
                    fma2u(acc1[r][c], s1a, wv.x);
                    ull s1b = relu2u(add2u(aI[r].y, bJ.y));
                    fma2u(acc1[r][c], s1b, wv.y);
                    ull s2a = relu2u(add2u(pJ.x, bI[r].x));
                    fma2u(acc2[r][c], s2a, wv.x);
                    ull s2b = relu2u(add2u(pJ.y, bI[r].y));
                    fma2u(acc2[r][c], s2b, wv.y);
                }
            }
        }
    };

    // chunk c lives in stage c % 3
    asm volatile("cp.async.wait_group 2;"); __syncthreads();
    compute_chunk(shB + 0 * STAGEW, w2s + 0);

    asm volatile("cp.async.wait_group 1;"); __syncthreads();
    issue_chunk(3, 0);                     // stage0 free: all warps past compute0
    compute_chunk(shB + 1 * STAGEW, w2s + 16);

    asm volatile("cp.async.wait_group 1;"); __syncthreads();
    compute_chunk(shB + 2 * STAGEW, w2s + 32);

    asm volatile("cp.async.wait_group 0;"); __syncthreads();
    compute_chunk(shB + 0 * STAGEW, w2s + 48);

    const float b2v = b2[0];
    float* outB = out + (size_t)b * NSEQ * NSEQ;

    // Final values + direct (coalesced) store of out[I+i][J+j]
    float v[4][4];
    #pragma unroll
    for (int r = 0; r < 4; r++) {
        int i = ty + 16 * r;
        #pragma unroll
        for (int c = 0; c < 4; c++) {
            int j = tx + 16 * c;
            float s1 = lo32(acc1[r][c]) + hi32(acc1[r][c]) + b2v;
            float s2 = lo32(acc2[r][c]) + hi32(acc2[r][c]) + b2v;
            float vv = -0.5f * (fast_tanh(s1) + fast_tanh(s2));
            v[r][c] = vv;
            outB[(I * 64 + i) * NSEQ + (J * 64 + j)] = vv;
        }
    }

    // Mirror store out[J+j][I+i] via padded smem transpose (stride 65).
    __syncthreads();                 // all warps done reading stage0
    float* vs = shB;                 // reuse: 64 * 65 = 4160 words < STAGEW
    #pragma unroll
    for (int r = 0; r < 4; r++)
        #pragma unroll
        for (int c = 0; c < 4; c++)
            vs[(ty + 16 * r) * 65 + (tx + 16 * c)] = v[r][c];
    __syncthreads();
    #pragma unroll
    for (int r = 0; r < 4; r++) {
        int jj = ty + 16 * r;
        #pragma unroll
        for (int c = 0; c < 4; c++) {
            int ii = tx + 16 * c;
            outB[(J * 64 + jj) * NSEQ + (I * 64 + ii)] = vs[ii * 65 + jj];
        }
    }
}

// ---------------------------------------------------------------------------
extern "C" void kernel_launch(void* const* d_in, const int* in_sizes, int n_in,
                              void* d_out, int out_size)
{
    const float* emb = (const float*)d_in[0];
    const float* W1  = (const float*)d_in[1];
    const float* b1  = (const float*)d_in[2];
    const float* W2  = (const float*)d_in[3];
    const float* b2  = (const float*)d_in[4];
    float* out = (float*)d_out;

    const int smemA = 2 * 64 * 130 * 4;                  // 66560
    const int smemB = (NSTAGE * STAGEW + 64) * 4;        // 61696

    cudaFuncSetAttribute(precompute_kernel,
                         cudaFuncAttributeMaxDynamicSharedMemorySize, smemA);
    cudaFuncSetAttribute(pair_sym_kernel,
                         cudaFuncAttributeMaxDynamicSharedMemorySize, smemB);

    precompute_kernel<<<dim3(64, 2), 256, smemA>>>(emb, W1, b1);
    pair_sym_kernel<<<dim3(136, BATCH), 256, smemB>>>(W2, b2, out);
}

// round 9
// speedup vs baseline: 1.4750x; 1.0522x over previous
#include <cuda_runtime.h>
#include <cuda_bf16.h>
#include <cstdint>
#include <math.h>

// Problem constants: B=4, N=1024, D=128, H=64
#define BATCH 4
#define NSEQ  1024
#define DDIM  128
#define HDIM  64
#define BN    (BATCH * NSEQ)   // 4096

typedef unsigned long long ull;

// Projections stored [row][h] row-major: cp.async 16B chunks fill smem directly.
__device__ float g_pre[BN * HDIM];   // emb @ Wa + b1
__device__ float g_hj [BN * HDIM];   // emb @ Wb

// ---------------------------------------------------------------------------
// Packed f32x2 helpers — pure b64 ("l") flow.
// ---------------------------------------------------------------------------
__device__ __forceinline__ ull add2u(ull a, ull b) {
    ull r;
    asm("add.rn.f32x2 %0, %1, %2;" : "=l"(r) : "l"(a), "l"(b));
    return r;
}
__device__ __forceinline__ void fma2u(ull& d, ull a, ull b) {
    asm("fma.rn.f32x2 %0, %1, %2, %0;" : "+l"(d) : "l"(a), "l"(b));
}
__device__ __forceinline__ ull relu2u(ull a) {
    ull r;
    asm("{\n\t.reg .f32 lo, hi;\n\t"
        "mov.b64 {lo, hi}, %1;\n\t"
        "max.f32 lo, lo, 0f00000000;\n\t"
        "max.f32 hi, hi, 0f00000000;\n\t"
        "mov.b64 %0, {lo, hi};\n\t}"
        : "=l"(r) : "l"(a));
    return r;
}
__device__ __forceinline__ float lo32(ull a) {
    return __uint_as_float((unsigned int)(a & 0xffffffffull));
}
__device__ __forceinline__ float hi32(ull a) {
    return __uint_as_float((unsigned int)(a >> 32));
}

__device__ __forceinline__ float fast_tanh(float x) {
    float e = __expf(2.0f * x);
    return 1.0f - __fdividef(2.0f, e + 1.0f);
}

__device__ __forceinline__ void cp16(unsigned int dst, const float* src) {
    asm volatile("cp.async.ca.shared.global [%0], [%1], 16;"
                 :: "r"(dst), "l"(src));
}

// ---------------------------------------------------------------------------
// Kernel A: projections (unchanged from R5).
// Grid (64, 2): x = 64-row tile, y = half (0 -> Wa/pre (+b1), 1 -> Wb/hj).
// dyn smem = 2 * 64*130 * 4 = 66560 B
// ---------------------------------------------------------------------------
__global__ __launch_bounds__(256) void precompute_kernel(
    const float* __restrict__ emb, const float* __restrict__ W1,
    const float* __restrict__ b1)
{
    extern __shared__ float sh[];
    float* w1t = sh;              // 64 cols * 130
    float* es  = sh + 64 * 130;   // 64 rows * 130
    const int t = threadIdx.x;
    const int row0 = blockIdx.x * 64;
    const int half = blockIdx.y;  // 0 = Wa, 1 = Wb

    for (int idx = t; idx < 64 * 128; idx += 256) {
        int c = idx & 63, d = idx >> 6;
        w1t[c * 130 + d] = W1[(half * 128 + d) * 64 + c];
    }
    for (int idx = t; idx < 64 * 128; idx += 256) {
        int d = idx & 127, r = idx >> 7;
        es[r * 130 + d] = emb[(row0 + r) * 128 + d];
    }
    __syncthreads();

    const int lane = t & 31;
    const int w    = t >> 5;
    const int c0   = w * 8;

    ull acc[2][8];
    #pragma unroll
    for (int rr = 0; rr < 2; rr++)
        #pragma unroll
        for (int cc = 0; cc < 8; cc++)
            acc[rr][cc] = 0ull;

    const float* e0p = es + lane * 130;
    const float* e1p = es + (lane + 32) * 130;

    #pragma unroll 4
    for (int d = 0; d < 128; d += 2) {
        ull e0 = *(const ull*)(e0p + d);
        ull e1 = *(const ull*)(e1p + d);
        #pragma unroll
        for (int cc = 0; cc < 8; cc++) {
            ull wv = *(const ull*)(w1t + (c0 + cc) * 130 + d);
            fma2u(acc[0][cc], e0, wv);
            fma2u(acc[1][cc], e1, wv);
        }
    }

    float* dst = half ? g_hj : g_pre;
    #pragma unroll
    for (int rr = 0; rr < 2; rr++) {
        int rowg = row0 + lane + 32 * rr;
        float s[8];
        #pragma unroll
        for (int cc = 0; cc < 8; cc++) {
            s[cc] = lo32(acc[rr][cc]) + hi32(acc[rr][cc]);
            if (half == 0) s[cc] += b1[c0 + cc];
        }
        *(float4*)(dst + rowg * 64 + c0)     = make_float4(s[0], s[1], s[2], s[3]);
        *(float4*)(dst + rowg * 64 + c0 + 4) = make_float4(s[4], s[5], s[6], s[7]);
    }
}

// ---------------------------------------------------------------------------
// Kernel B: fused pairwise core + tanh + symmetrize + negate.
// ONE-SHOT tile load: all 4 arrays x 64 rows x 64 h resident in smem,
// single cp.async group + ONE barrier, then an uninterrupted math phase.
// Row stride 68 words (64 h + 4 pad): LDS.128 at 68*tx -> 4*tx mod 32,
// conflict-free; i-side loads are warp-broadcast.
// dyn smem = (4*64*68 + 64) * 4 = 69888 B  -> 2 CTAs/SM
// ---------------------------------------------------------------------------
#define TSTRIDE 68
#define ARRW    (64 * TSTRIDE)       // 4352 words per array

__global__ __launch_bounds__(256, 2) void pair_sym_kernel(
    const float* __restrict__ W2, const float* __restrict__ b2,
    float* __restrict__ out)
{
    extern __shared__ float shB[];
    float* w2s = shB + 4 * ARRW;     // 64

    const int t = threadIdx.x;
    const int b = blockIdx.y;

    // Decode unordered pair (I, J), I <= J
    int p = blockIdx.x;
    int I = 0;
    while (p >= 16 - I) { p -= 16 - I; I++; }
    const int J = I + p;

    const int baseI = b * NSEQ + I * 64;
    const int baseJ = b * NSEQ + J * 64;

    // Fill: 64-thread group per array, 16 x 16B cp.async per thread.
    const int arr = t >> 6;          // 0..3
    const int sub = t & 63;
    const float* srcbase =
        (arr == 0) ? g_pre + baseI * 64 :
        (arr == 1) ? g_hj  + baseI * 64 :
        (arr == 2) ? g_pre + baseJ * 64 :
                     g_hj  + baseJ * 64;
    const unsigned int sbase = (unsigned int)__cvta_generic_to_shared(shB);
    const unsigned int dbase = sbase + (unsigned int)(arr * ARRW) * 4u;

    #pragma unroll
    for (int e = 0; e < 16; e++) {
        int idx = sub + 64 * e;          // 0..1023 chunk id
        int row = idx >> 4;              // 64 rows
        int q   = (idx & 15) * 4;        // 16 quads of 4 h
        cp16(dbase + (unsigned int)(row * TSTRIDE + q) * 4u, srcbase + row * 64 + q);
    }
    asm volatile("cp.async.commit_group;");

    if (t < 64) w2s[t] = W2[t];

    const int tx = t & 15;
    const int ty = t >> 4;

    ull acc1[4][4], acc2[4][4];
    #pragma unroll
    for (int r = 0; r < 4; r++)
        #pragma unroll
        for (int c = 0; c < 4; c++) { acc1[r][c] = 0ull; acc2[r][c] = 0ull; }

    asm volatile("cp.async.wait_group 0;");
    __syncthreads();                 // the ONLY pre-epilogue barrier

    const float* pAI = shB            + ty * TSTRIDE;   // preI rows
    const float* pHI = shB + ARRW     + ty * TSTRIDE;   // hjI rows
    const float* pPJ = shB + 2 * ARRW + tx * TSTRIDE;   // preJ rows
    const float* pHJ = shB + 3 * ARRW + tx * TSTRIDE;   // hjJ rows

    #pragma unroll 2
    for (int hh = 0; hh < HDIM; hh += 4) {
        ulonglong2 wv = *(const ulonglong2*)(w2s + hh);
        ulonglong2 aI[4], bI[4];
        #pragma unroll
        for (int r = 0; r < 4; r++) {
            aI[r] = *(const ulonglong2*)(pAI + (16 * r) * TSTRIDE + hh);
            bI[r] = *(const ulonglong2*)(pHI + (16 * r) * TSTRIDE + hh);
        }
        #pragma unroll
        for (int c = 0; c < 4; c++) {
            ulonglong2 pJ = *(const ulonglong2*)(pPJ + (16 * c) * TSTRIDE + hh);
            ulonglong2 bJ = *(const ulonglong2*)(pHJ + (16 * c) * TSTRIDE + hh);
            #pragma unroll
            for (int r = 0; r < 4; r++) {
                ull s1a = relu2u(add2u(aI[r].x, bJ.x));
                fma2u(acc1[r][c], s1a, wv.x);
                ull s1b = relu2u(add2u(aI[r].y, bJ.y));
                fma2u(acc1[r][c], s1b, wv.y);
                ull s2a = relu2u(add2u(pJ.x, bI[r].x));
                fma2u(acc2[r][c], s2a, wv.x);
                ull s2b = relu2u(add2u(pJ.y, bI[r].y));
                fma2u(acc2[r][c], s2b, wv.y);
            }
        }
    }

    const float b2v = b2[0];
    float* outB = out + (size_t)b * NSEQ * NSEQ;

    // Final values + direct (coalesced) store of out[I+i][J+j]
    float v[4][4];
    #pragma unroll
    for (int r = 0; r < 4; r++) {
        int i = ty + 16 * r;
        #pragma unroll
        for (int c = 0; c < 4; c++) {
            int j = tx + 16 * c;
            float s1 = lo32(acc1[r][c]) + hi32(acc1[r][c]) + b2v;
            float s2 = lo32(acc2[r][c]) + hi32(acc2[r][c]) + b2v;
            float vv = -0.5f * (fast_tanh(s1) + fast_tanh(s2));
            v[r][c] = vv;
            outB[(I * 64 + i) * NSEQ + (J * 64 + j)] = vv;
        }
    }

    // Mirror store out[J+j][I+i] via padded smem transpose (stride 65).
    __syncthreads();                 // all warps done reading tiles
    float* vs = shB;                 // reuse: 64 * 65 = 4160 words
    #pragma unroll
    for (int r = 0; r < 4; r++)
        #pragma unroll
        for (int c = 0; c < 4; c++)
            vs[(ty + 16 * r) * 65 + (tx + 16 * c)] = v[r][c];
    __syncthreads();
    #pragma unroll
    for (int r = 0; r < 4; r++) {
        int jj = ty + 16 * r;
        #pragma unroll
        for (int c = 0; c < 4; c++) {
            int ii = tx + 16 * c;
            outB[(J * 64 + jj) * NSEQ + (I * 64 + ii)] = vs[ii * 65 + jj];
        }
    }
}

// ---------------------------------------------------------------------------
extern "C" void kernel_launch(void* const* d_in, const int* in_sizes, int n_in,
                              void* d_out, int out_size)
{
    const float* emb = (const float*)d_in[0];
    const float* W1  = (const float*)d_in[1];
    const float* b1  = (const float*)d_in[2];
    const float* W2  = (const float*)d_in[3];
    const float* b2  = (const float*)d_in[4];
    float* out = (float*)d_out;

    const int smemA = 2 * 64 * 130 * 4;              // 66560
    const int smemB = (4 * ARRW + 64) * 4;           // 69888

    cudaFuncSetAttribute(precompute_kernel,
                         cudaFuncAttributeMaxDynamicSharedMemorySize, smemA);
    cudaFuncSetAttribute(pair_sym_kernel,
                         cudaFuncAttributeMaxDynamicSharedMemorySize, smemB);

    precompute_kernel<<<dim3(64, 2), 256, smemA>>>(emb, W1, b1);
    pair_sym_kernel<<<dim3(136, BATCH), 256, smemB>>>(W2, b2, out);
}